// round 7
// baseline (speedup 1.0000x reference)
#include <cuda_runtime.h>
#include <cuda_bf16.h>
#include <stdint.h>
#include <math.h>

#define BATCH 4
#define SLEN 2048
#define DDIM 1024
#define NHEAD 16
#define DKH 64
#define MROWS (BATCH * SLEN)  // 8192

// Scratch (alloc-free rule: __device__ globals)
__device__ __nv_bfloat16 g_Xh[MROWS * DDIM];
__device__ __nv_bfloat16 g_Xl[MROWS * DDIM];
__device__ __nv_bfloat16 g_Wh[4 * DDIM * DDIM];
__device__ __nv_bfloat16 g_Wl[4 * DDIM * DDIM];
__device__ __nv_bfloat16 g_Qh[MROWS * DDIM];
__device__ __nv_bfloat16 g_Ql[MROWS * DDIM];
__device__ __nv_bfloat16 g_Kh[MROWS * DDIM];
__device__ __nv_bfloat16 g_Kl[MROWS * DDIM];
__device__ __nv_bfloat16 g_Vh[MROWS * DDIM];
__device__ __nv_bfloat16 g_Vl[MROWS * DDIM];
__device__ __nv_bfloat16 g_Ah[MROWS * DDIM];
__device__ __nv_bfloat16 g_Al[MROWS * DDIM];

// ===================== common helpers =====================
__device__ __forceinline__ uint32_t smem_u32(const void* p) {
    uint32_t a;
    asm("{ .reg .u64 t; cvta.to.shared.u64 t, %1; cvt.u32.u64 %0, t; }"
        : "=r"(a) : "l"(p));
    return a;
}

__device__ __forceinline__ void mma16816(float* c, const uint32_t* a, const uint32_t* b) {
    asm volatile(
        "mma.sync.aligned.m16n8k16.row.col.f32.bf16.bf16.f32 "
        "{%0,%1,%2,%3}, {%4,%5,%6,%7}, {%8,%9}, {%0,%1,%2,%3};"
        : "+f"(c[0]), "+f"(c[1]), "+f"(c[2]), "+f"(c[3])
        : "r"(a[0]), "r"(a[1]), "r"(a[2]), "r"(a[3]), "r"(b[0]), "r"(b[1]));
}

__device__ __forceinline__ uint32_t packbf(float x, float y) {
    uint32_t r;
    asm("cvt.rn.bf16x2.f32 %0, %1, %2;" : "=r"(r) : "f"(y), "f"(x));
    return r;
}
__device__ __forceinline__ void unpackbf(uint32_t w, float& x, float& y) {
    x = __int_as_float(w << 16);
    y = __int_as_float(w & 0xffff0000u);
}

__device__ __forceinline__ void split4(float4 v, uint2& hi, uint2& lo) {
    uint32_t h0 = packbf(v.x, v.y), h1 = packbf(v.z, v.w);
    float a, b, c, d;
    unpackbf(h0, a, b);
    unpackbf(h1, c, d);
    hi.x = h0; hi.y = h1;
    lo.x = packbf(v.x - a, v.y - b);
    lo.y = packbf(v.z - c, v.w - d);
}

// fast exp2 on fma/alu pipes (input <= 0); rel err ~2e-7
__device__ __forceinline__ float fexp2(float t) {
    t = fmaxf(t, -125.f);
    float fi = floorf(t);
    float f = t - fi;
    float p = 1.5353362e-4f;
    p = fmaf(p, f, 1.3398874e-3f);
    p = fmaf(p, f, 9.6184374e-3f);
    p = fmaf(p, f, 5.5503325e-2f);
    p = fmaf(p, f, 2.4022648e-1f);
    p = fmaf(p, f, 6.9314720e-1f);
    p = fmaf(p, f, 1.0f);
    return __int_as_float(__float_as_int(p) + ((int)fi << 23));
}

#define LDSM4(r0, r1, r2, r3, addr)                                            \
    asm volatile("ldmatrix.sync.aligned.m8n8.x4.shared.b16 {%0,%1,%2,%3}, [%4];" \
                 : "=r"(r0), "=r"(r1), "=r"(r2), "=r"(r3) : "r"(addr))
#define LDSM4T(r0, r1, r2, r3, addr)                                           \
    asm volatile("ldmatrix.sync.aligned.m8n8.x4.trans.shared.b16 {%0,%1,%2,%3}, [%4];" \
                 : "=r"(r0), "=r"(r1), "=r"(r2), "=r"(r3) : "r"(addr))

#define CP16(dst, src) \
    asm volatile("cp.async.cg.shared.global [%0], [%1], 16;" :: "r"(dst), "l"(src))
#define CP_COMMIT() asm volatile("cp.async.commit_group;")
#define CP_WAIT(n) asm volatile("cp.async.wait_group %0;" :: "n"(n))

// ===================== pre-split: fp32 -> bf16 hi/lo =====================
__global__ __launch_bounds__(256) void conv_all(const float* __restrict__ emb,
                                                const float* __restrict__ Wq,
                                                const float* __restrict__ Wk,
                                                const float* __restrict__ Wv,
                                                const float* __restrict__ Wo) {
    const size_t NX = (size_t)MROWS * DDIM / 4;  // 2097152 float4
    size_t i = (size_t)blockIdx.x * 256 + threadIdx.x;
    float4 v;
    uint2 hi, lo;
    uint2 *dh, *dl;
    if (i < NX) {
        v = ((const float4*)emb)[i];
        dh = (uint2*)g_Xh + i;
        dl = (uint2*)g_Xl + i;
    } else {
        size_t j = i - NX;
        size_t w = j >> 18;  // 262144 float4 per weight matrix
        size_t rem = j & 262143;
        const float* W = (w == 0) ? Wq : (w == 1) ? Wk : (w == 2) ? Wv : Wo;
        v = ((const float4*)W)[rem];
        dh = (uint2*)g_Wh + j;
        dl = (uint2*)g_Wl + j;
    }
    split4(v, hi, lo);
    *dh = hi;
    *dl = lo;
}

// ===================== GEMM: Y = X @ W^T  (pure cp.async pipeline) =====================
// Inputs pre-split bf16: Xh/Xl [M,K], Wh/Wl [N,K]. CTA 128x128, 8 warps (2x4).
#define KC 32
#define NS (DDIM / KC)          // 32 stages
#define ROWB 80                 // bytes per smem row (32 bf16 + pad): conflict-free LDSM
#define GHALF 10240             // 128 rows * 80 B: one of Ah/Al/Bh/Bl
#define STAGE_B (4 * GHALF)     // 40960 B
#define NSTG 3
#define GEMM_SMEM (NSTG * STAGE_B)  // 122880 B

template <bool SPLIT_OUT>
__device__ __forceinline__ void mma_gemm(const __nv_bfloat16* __restrict__ Xh,
                                         const __nv_bfloat16* __restrict__ Xl,
                                         const __nv_bfloat16* __restrict__ Wh,
                                         const __nv_bfloat16* __restrict__ Wl,
                                         float* __restrict__ Yf,
                                         __nv_bfloat16* __restrict__ Yh,
                                         __nv_bfloat16* __restrict__ Yl) {
    extern __shared__ char smem_raw[];
    const uint32_t smb = smem_u32(smem_raw);

    const int tid = threadIdx.x;
    const int warp = tid >> 5, lane = tid & 31;
    const int wm = warp >> 2;      // 0..1 -> m offset wm*64
    const int wn = warp & 3;       // 0..3 -> n offset wn*32
    const int g = lane >> 2;
    const int tq = lane & 3;
    const int mi = lane >> 3;
    const int r8 = lane & 7;
    const int bm = blockIdx.y * 128;
    const int bn = blockIdx.x * 128;

    float acc[4][4][4];
#pragma unroll
    for (int i = 0; i < 4; i++)
#pragma unroll
        for (int j = 0; j < 4; j++)
#pragma unroll
            for (int r = 0; r < 4; r++) acc[i][j][r] = 0.f;

    // cp.async one K-stage into buffer `buf`: 4 arrays x 128 rows x 4 x 16B
    auto issue_stage = [&](int s, int buf) {
        const int k0 = s * KC;
        const uint32_t db = smb + buf * STAGE_B;
#pragma unroll
        for (int it = 0; it < 8; it++) {
            int idx = tid + it * 256;
            int arr = idx >> 9;
            int rem = idx & 511;
            int row = rem >> 2;
            int c16 = rem & 3;
            const __nv_bfloat16* src;
            if (arr == 0)      src = Xh + (size_t)(bm + row) * DDIM + k0 + c16 * 8;
            else if (arr == 1) src = Xl + (size_t)(bm + row) * DDIM + k0 + c16 * 8;
            else if (arr == 2) src = Wh + (size_t)(bn + row) * DDIM + k0 + c16 * 8;
            else               src = Wl + (size_t)(bn + row) * DDIM + k0 + c16 * 8;
            CP16(db + arr * GHALF + row * ROWB + c16 * 16, src);
        }
    };

    auto compute = [&](int buf) {
        const uint32_t Ah = smb + buf * STAGE_B;
        const uint32_t Bh = Ah + 2 * GHALF;
#pragma unroll
        for (int kt = 0; kt < 2; kt++) {
            uint32_t ah[4][4], al[4][4], bh[2][4], bl[2][4];
#pragma unroll
            for (int mt = 0; mt < 4; mt++) {
                uint32_t ar = Ah + (wm * 64 + mt * 16 + (mi & 1) * 8 + r8) * ROWB +
                              (kt * 16 + (mi >> 1) * 8) * 2;
                LDSM4(ah[mt][0], ah[mt][1], ah[mt][2], ah[mt][3], ar);
                LDSM4(al[mt][0], al[mt][1], al[mt][2], al[mt][3], ar + GHALF);
            }
#pragma unroll
            for (int j = 0; j < 2; j++) {
                uint32_t br = Bh + (wn * 32 + j * 16 + (mi >> 1) * 8 + r8) * ROWB +
                              (kt * 16 + (mi & 1) * 8) * 2;
                LDSM4(bh[j][0], bh[j][1], bh[j][2], bh[j][3], br);
                LDSM4(bl[j][0], bl[j][1], bl[j][2], bl[j][3], br + GHALF);
            }
#pragma unroll
            for (int mt = 0; mt < 4; mt++)
#pragma unroll
                for (int j = 0; j < 2; j++)
#pragma unroll
                    for (int h = 0; h < 2; h++)
                        mma16816(acc[mt][2 * j + h], ah[mt], bh[j] + 2 * h);
#pragma unroll
            for (int mt = 0; mt < 4; mt++)
#pragma unroll
                for (int j = 0; j < 2; j++)
#pragma unroll
                    for (int h = 0; h < 2; h++)
                        mma16816(acc[mt][2 * j + h], ah[mt], bl[j] + 2 * h);
#pragma unroll
            for (int mt = 0; mt < 4; mt++)
#pragma unroll
                for (int j = 0; j < 2; j++)
#pragma unroll
                    for (int h = 0; h < 2; h++)
                        mma16816(acc[mt][2 * j + h], al[mt], bh[j] + 2 * h);
        }
    };

    issue_stage(0, 0);
    CP_COMMIT();
    issue_stage(1, 1);
    CP_COMMIT();

    for (int s = 0; s < NS; s++) {
        if (s < NS - 1) { CP_WAIT(1); } else { CP_WAIT(0); }
        __syncthreads();
        if (s + 2 < NS) {
            issue_stage(s + 2, (s + 2) % NSTG);
            CP_COMMIT();
        }
        compute(s % NSTG);
    }

#pragma unroll
    for (int mt = 0; mt < 4; mt++) {
        const int row = bm + wm * 64 + mt * 16 + g;
#pragma unroll
        for (int nt = 0; nt < 4; nt++) {
            const int col = bn + wn * 32 + nt * 8 + tq * 2;
            if (SPLIT_OUT) {
                uint32_t* Yh32 = (uint32_t*)Yh;
                uint32_t* Yl32 = (uint32_t*)Yl;
                float a, b;
                uint32_t h0 = packbf(acc[mt][nt][0], acc[mt][nt][1]);
                unpackbf(h0, a, b);
                uint32_t l0 = packbf(acc[mt][nt][0] - a, acc[mt][nt][1] - b);
                Yh32[((size_t)row * DDIM + col) >> 1] = h0;
                Yl32[((size_t)row * DDIM + col) >> 1] = l0;
                uint32_t h1 = packbf(acc[mt][nt][2], acc[mt][nt][3]);
                unpackbf(h1, a, b);
                uint32_t l1 = packbf(acc[mt][nt][2] - a, acc[mt][nt][3] - b);
                Yh32[((size_t)(row + 8) * DDIM + col) >> 1] = h1;
                Yl32[((size_t)(row + 8) * DDIM + col) >> 1] = l1;
            } else {
                *(float2*)(Yf + (size_t)row * DDIM + col) =
                    make_float2(acc[mt][nt][0], acc[mt][nt][1]);
                *(float2*)(Yf + (size_t)(row + 8) * DDIM + col) =
                    make_float2(acc[mt][nt][2], acc[mt][nt][3]);
            }
        }
    }
}

__global__ __launch_bounds__(256, 1) void qkv_mma() {
    const int z = blockIdx.z;
    const __nv_bfloat16* Wh = g_Wh + (size_t)z * DDIM * DDIM;
    const __nv_bfloat16* Wl = g_Wl + (size_t)z * DDIM * DDIM;
    __nv_bfloat16* Yh = (z == 0) ? g_Qh : (z == 1) ? g_Kh : g_Vh;
    __nv_bfloat16* Yl = (z == 0) ? g_Ql : (z == 1) ? g_Kl : g_Vl;
    mma_gemm<true>(g_Xh, g_Xl, Wh, Wl, nullptr, Yh, Yl);
}

__global__ __launch_bounds__(256, 1) void oproj_mma(float* __restrict__ out) {
    mma_gemm<false>(g_Ah, g_Al, g_Wh + (size_t)3 * DDIM * DDIM,
                    g_Wl + (size_t)3 * DDIM * DDIM, out, nullptr, nullptr);
}

// ===================== Flash attention: 256 q-rows/CTA, 8 warps x 32 rows, 3-stage KV ======
#define NT (SLEN / 64)        // 32 kv tiles
#define RSTR 144              // smem row stride bytes
#define KVARR (64 * RSTR)     // 9216 B
#define KVBUF (4 * KVARR)     // 36864 B: Kh,Kl,Vh,Vl
#define QARR (256 * RSTR)     // 36864 B
#define ATT_SMEM (2 * QARR + 3 * KVBUF)  // 184320 B

__global__ __launch_bounds__(256, 1) void attn_mma() {
    extern __shared__ char smem_raw[];
    const uint32_t smb = smem_u32(smem_raw);
    const uint32_t q_u32 = smb;
    const uint32_t kv_u32 = smb + 2 * QARR;

    const int tid = threadIdx.x;
    const int wm = tid >> 5;
    const int lane = tid & 31;
    const int g = lane >> 2;
    const int tq = lane & 3;
    const int mi = lane >> 3;
    const int r8 = lane & 7;
    const int b = blockIdx.y >> 4;
    const int h = blockIdx.y & 15;
    const int q0 = blockIdx.x * 256;
    const size_t bS = (size_t)b * SLEN;
    const int hoff = h * DKH;

    // ---- Q loads (group 0) ----
#pragma unroll
    for (int p = 0; p < 2; p++) {
        int task = tid + p * 256;
        int arr = task >> 8, row = task & 255;
        const __nv_bfloat16* gp =
            (arr ? g_Ql : g_Qh) + (bS + q0 + row) * DDIM + hoff;
        uint32_t dst = q_u32 + arr * QARR + row * RSTR;
#pragma unroll
        for (int i = 0; i < 8; i++) CP16(dst + i * 16, gp + i * 8);
    }
    CP_COMMIT();

    auto load_kv = [&](int t, int bb) {
        int arr = tid >> 6, row = tid & 63;
        const __nv_bfloat16* gp =
            (arr == 0 ? g_Kh : arr == 1 ? g_Kl : arr == 2 ? g_Vh : g_Vl) +
            (bS + t * 64 + row) * DDIM + hoff;
        uint32_t dst = kv_u32 + bb * KVBUF + arr * KVARR + row * RSTR;
#pragma unroll
        for (int i = 0; i < 8; i++) CP16(dst + i * 16, gp + i * 8);
    };

    load_kv(0, 0);
    CP_COMMIT();
    load_kv(1, 1);
    CP_COMMIT();

    float s[2][8][4];
    float o[2][8][4];
    float ms[4] = {-1e30f, -1e30f, -1e30f, -1e30f};
    float l[4] = {0.f, 0.f, 0.f, 0.f};
#pragma unroll
    for (int mt = 0; mt < 2; mt++)
#pragma unroll
        for (int j = 0; j < 8; j++)
#pragma unroll
            for (int c = 0; c < 4; c++) o[mt][j][c] = 0.f;
    const float SCL = 0.125f * 1.4426950408889634f;

    for (int t = 0; t < NT; t++) {
        if (t < NT - 1) { CP_WAIT(1); } else { CP_WAIT(0); }
        __syncthreads();
        if (t + 2 < NT) {
            load_kv(t + 2, (t + 2) % 3);
            CP_COMMIT();
        }

        const uint32_t khb = kv_u32 + (t % 3) * KVBUF;
        const uint32_t vhb = khb + 2 * KVARR;

        // ---- S = Q K^T (3 term-major passes) ----
#pragma unroll
        for (int mt = 0; mt < 2; mt++)
#pragma unroll
            for (int j = 0; j < 8; j++)
#pragma unroll
                for (int c = 0; c < 4; c++) s[mt][j][c] = 0.f;
#pragma unroll
        for (int kt = 0; kt < 4; kt++) {
            uint32_t bh[4][4], bl[4][4];
#pragma unroll
            for (int j2 = 0; j2 < 4; j2++) {
                uint32_t addr = khb + (16 * j2 + (mi >> 1) * 8 + r8) * RSTR +
                                (kt * 16 + (mi & 1) * 8) * 2;
                LDSM4(bh[j2][0], bh[j2][1], bh[j2][2], bh[j2][3], addr);
                LDSM4(bl[j2][0], bl[j2][1], bl[j2][2], bl[j2][3], addr + KVARR);
            }
#pragma unroll
            for (int mt = 0; mt < 2; mt++) {
                uint32_t qaddr = q_u32 + (wm * 32 + mt * 16 + (mi & 1) * 8 + r8) * RSTR +
                                 (kt * 16 + (mi >> 1) * 8) * 2;
                uint32_t ah[4], al[4];
                LDSM4(ah[0], ah[1], ah[2], ah[3], qaddr);
                LDSM4(al[0], al[1], al[2], al[3], qaddr + QARR);
#pragma unroll
                for (int j2 = 0; j2 < 4; j2++) {
                    mma16816(s[mt][2 * j2], ah, bh[j2]);
                    mma16816(s[mt][2 * j2 + 1], ah, bh[j2] + 2);
                }
#pragma unroll
                for (int j2 = 0; j2 < 4; j2++) {
                    mma16816(s[mt][2 * j2], ah, bl[j2]);
                    mma16816(s[mt][2 * j2 + 1], ah, bl[j2] + 2);
                }
#pragma unroll
                for (int j2 = 0; j2 < 4; j2++) {
                    mma16816(s[mt][2 * j2], al, bh[j2]);
                    mma16816(s[mt][2 * j2 + 1], al, bh[j2] + 2);
                }
            }
        }

        // ---- online softmax ----
#pragma unroll
        for (int mt = 0; mt < 2; mt++) {
            float mx0 = -1e30f, mx1 = -1e30f;
#pragma unroll
            for (int j = 0; j < 8; j++) {
                mx0 = fmaxf(mx0, fmaxf(s[mt][j][0], s[mt][j][1]));
                mx1 = fmaxf(mx1, fmaxf(s[mt][j][2], s[mt][j][3]));
            }
            mx0 = fmaxf(mx0, __shfl_xor_sync(0xffffffffu, mx0, 1));
            mx0 = fmaxf(mx0, __shfl_xor_sync(0xffffffffu, mx0, 2));
            mx1 = fmaxf(mx1, __shfl_xor_sync(0xffffffffu, mx1, 1));
            mx1 = fmaxf(mx1, __shfl_xor_sync(0xffffffffu, mx1, 2));
            float ns0 = fmaxf(ms[2 * mt], mx0 * SCL);
            float ns1 = fmaxf(ms[2 * mt + 1], mx1 * SCL);
            float al0 = fexp2(ms[2 * mt] - ns0);
            float al1 = fexp2(ms[2 * mt + 1] - ns1);
            ms[2 * mt] = ns0;
            ms[2 * mt + 1] = ns1;
            float rs0 = 0.f, rs1 = 0.f;
#pragma unroll
            for (int j = 0; j < 8; j++) {
                float p0 = fexp2(fmaf(s[mt][j][0], SCL, -ns0));
                float p1 = fexp2(fmaf(s[mt][j][1], SCL, -ns0));
                float p2 = fexp2(fmaf(s[mt][j][2], SCL, -ns1));
                float p3 = fexp2(fmaf(s[mt][j][3], SCL, -ns1));
                s[mt][j][0] = p0; s[mt][j][1] = p1;
                s[mt][j][2] = p2; s[mt][j][3] = p3;
                rs0 += p0 + p1;
                rs1 += p2 + p3;
            }
            rs0 += __shfl_xor_sync(0xffffffffu, rs0, 1);
            rs0 += __shfl_xor_sync(0xffffffffu, rs0, 2);
            rs1 += __shfl_xor_sync(0xffffffffu, rs1, 1);
            rs1 += __shfl_xor_sync(0xffffffffu, rs1, 2);
            l[2 * mt] = l[2 * mt] * al0 + rs0;
            l[2 * mt + 1] = l[2 * mt + 1] * al1 + rs1;
#pragma unroll
            for (int j = 0; j < 8; j++) {
                o[mt][j][0] *= al0; o[mt][j][1] *= al0;
                o[mt][j][2] *= al1; o[mt][j][3] *= al1;
            }
        }

        // ---- O += P V ----
#pragma unroll
        for (int kt = 0; kt < 4; kt++) {
            uint32_t vh[4][4], vl[4][4];
#pragma unroll
            for (int j2 = 0; j2 < 4; j2++) {
                uint32_t addr = vhb + (kt * 16 + (mi & 1) * 8 + r8) * RSTR +
                                (16 * j2 + (mi >> 1) * 8) * 2;
                LDSM4T(vh[j2][0], vh[j2][1], vh[j2][2], vh[j2][3], addr);
                LDSM4T(vl[j2][0], vl[j2][1], vl[j2][2], vl[j2][3], addr + KVARR);
            }
#pragma unroll
            for (int mt = 0; mt < 2; mt++) {
                uint32_t aph[4], apl[4];
#pragma unroll
                for (int u = 0; u < 2; u++) {
                    const int j = 2 * kt + u;
                    uint32_t h0 = packbf(s[mt][j][0], s[mt][j][1]);
                    uint32_t h1 = packbf(s[mt][j][2], s[mt][j][3]);
                    float a, bb, c, d;
                    unpackbf(h0, a, bb);
                    unpackbf(h1, c, d);
                    aph[2 * u] = h0;
                    aph[2 * u + 1] = h1;
                    apl[2 * u] = packbf(s[mt][j][0] - a, s[mt][j][1] - bb);
                    apl[2 * u + 1] = packbf(s[mt][j][2] - c, s[mt][j][3] - d);
                }
#pragma unroll
                for (int j2 = 0; j2 < 4; j2++) {
                    mma16816(o[mt][2 * j2], aph, vh[j2]);
                    mma16816(o[mt][2 * j2 + 1], aph, vh[j2] + 2);
                }
#pragma unroll
                for (int j2 = 0; j2 < 4; j2++) {
                    mma16816(o[mt][2 * j2], aph, vl[j2]);
                    mma16816(o[mt][2 * j2 + 1], aph, vl[j2] + 2);
                }
#pragma unroll
                for (int j2 = 0; j2 < 4; j2++) {
                    mma16816(o[mt][2 * j2], apl, vh[j2]);
                    mma16816(o[mt][2 * j2 + 1], apl, vh[j2] + 2);
                }
            }
        }
    }

    // ---- epilogue: normalize, emit bf16 hi/lo for oproj ----
    uint32_t* Ah32 = (uint32_t*)g_Ah;
    uint32_t* Al32 = (uint32_t*)g_Al;
#pragma unroll
    for (int mt = 0; mt < 2; mt++) {
        const float inv0 = 1.f / l[2 * mt];
        const float inv1 = 1.f / l[2 * mt + 1];
        const int row0 = q0 + wm * 32 + mt * 16 + g;
#pragma unroll
        for (int j = 0; j < 8; j++) {
            const int col = hoff + j * 8 + tq * 2;
            float v0 = o[mt][j][0] * inv0, v1 = o[mt][j][1] * inv0;
            float v2 = o[mt][j][2] * inv1, v3 = o[mt][j][3] * inv1;
            float a, b;
            uint32_t h0 = packbf(v0, v1);
            unpackbf(h0, a, b);
            uint32_t l0 = packbf(v0 - a, v1 - b);
            Ah32[((bS + row0) * DDIM + col) >> 1] = h0;
            Al32[((bS + row0) * DDIM + col) >> 1] = l0;
            uint32_t h1 = packbf(v2, v3);
            unpackbf(h1, a, b);
            uint32_t l1 = packbf(v2 - a, v3 - b);
            Ah32[((bS + row0 + 8) * DDIM + col) >> 1] = h1;
            Al32[((bS + row0 + 8) * DDIM + col) >> 1] = l1;
        }
    }
}

// ======================= launch =======================
extern "C" void kernel_launch(void* const* d_in, const int* in_sizes, int n_in,
                              void* d_out, int out_size) {
    const float* emb = (const float*)d_in[0];
    const float* Wq  = (const float*)d_in[1];
    const float* Wk  = (const float*)d_in[2];
    const float* Wv  = (const float*)d_in[3];
    const float* Wo  = (const float*)d_in[4];
    float* out = (float*)d_out;

    cudaFuncSetAttribute(qkv_mma, cudaFuncAttributeMaxDynamicSharedMemorySize, GEMM_SMEM);
    cudaFuncSetAttribute(oproj_mma, cudaFuncAttributeMaxDynamicSharedMemorySize, GEMM_SMEM);
    cudaFuncSetAttribute(attn_mma, cudaFuncAttributeMaxDynamicSharedMemorySize, ATT_SMEM);

    // pre-split fp32 -> bf16 hi/lo
    const int NCONV = (MROWS * DDIM / 4 + 4 * DDIM * DDIM / 4) / 256;  // 12288
    conv_all<<<NCONV, 256>>>(emb, Wq, Wk, Wv, Wo);

    dim3 ggrid(DDIM / 128, MROWS / 128, 3);
    qkv_mma<<<ggrid, 256, GEMM_SMEM>>>();

    dim3 agrid(SLEN / 256, BATCH * NHEAD);
    attn_mma<<<agrid, 256, ATT_SMEM>>>();

    dim3 ogrid(DDIM / 128, MROWS / 128, 1);
    oproj_mma<<<ogrid, 256, GEMM_SMEM>>>(out);
}

// round 9
// speedup vs baseline: 1.0028x; 1.0028x over previous
#include <cuda_runtime.h>
#include <cuda_bf16.h>
#include <stdint.h>
#include <math.h>

#define BATCH 4
#define SLEN 2048
#define DDIM 1024
#define NHEAD 16
#define DKH 64
#define MROWS (BATCH * SLEN)  // 8192

// Scratch (alloc-free rule: __device__ globals)
__device__ __nv_bfloat16 g_Xh[MROWS * DDIM];
__device__ __nv_bfloat16 g_Xl[MROWS * DDIM];
__device__ __nv_bfloat16 g_Wh[4 * DDIM * DDIM];
__device__ __nv_bfloat16 g_Wl[4 * DDIM * DDIM];
__device__ __nv_bfloat16 g_Qh[MROWS * DDIM];
__device__ __nv_bfloat16 g_Ql[MROWS * DDIM];
__device__ __nv_bfloat16 g_Kh[MROWS * DDIM];
__device__ __nv_bfloat16 g_Kl[MROWS * DDIM];
__device__ __nv_bfloat16 g_Vh[MROWS * DDIM];
__device__ __nv_bfloat16 g_Vl[MROWS * DDIM];
__device__ __nv_bfloat16 g_Ah[MROWS * DDIM];
__device__ __nv_bfloat16 g_Al[MROWS * DDIM];

// ===================== common helpers =====================
__device__ __forceinline__ uint32_t smem_u32(const void* p) {
    uint32_t a;
    asm("{ .reg .u64 t; cvta.to.shared.u64 t, %1; cvt.u32.u64 %0, t; }"
        : "=r"(a) : "l"(p));
    return a;
}

__device__ __forceinline__ void mma16816(float* c, const uint32_t* a, const uint32_t* b) {
    asm volatile(
        "mma.sync.aligned.m16n8k16.row.col.f32.bf16.bf16.f32 "
        "{%0,%1,%2,%3}, {%4,%5,%6,%7}, {%8,%9}, {%0,%1,%2,%3};"
        : "+f"(c[0]), "+f"(c[1]), "+f"(c[2]), "+f"(c[3])
        : "r"(a[0]), "r"(a[1]), "r"(a[2]), "r"(a[3]), "r"(b[0]), "r"(b[1]));
}

__device__ __forceinline__ uint32_t packbf(float x, float y) {
    uint32_t r;
    asm("cvt.rn.bf16x2.f32 %0, %1, %2;" : "=r"(r) : "f"(y), "f"(x));
    return r;
}
__device__ __forceinline__ void unpackbf(uint32_t w, float& x, float& y) {
    x = __int_as_float(w << 16);
    y = __int_as_float(w & 0xffff0000u);
}

__device__ __forceinline__ void split4(float4 v, uint2& hi, uint2& lo) {
    uint32_t h0 = packbf(v.x, v.y), h1 = packbf(v.z, v.w);
    float a, b, c, d;
    unpackbf(h0, a, b);
    unpackbf(h1, c, d);
    hi.x = h0; hi.y = h1;
    lo.x = packbf(v.x - a, v.y - b);
    lo.y = packbf(v.z - c, v.w - d);
}

// fast exp2 on fma/alu pipes (input <= 0); rel err ~2e-7
__device__ __forceinline__ float fexp2(float t) {
    t = fmaxf(t, -125.f);
    float fi = floorf(t);
    float f = t - fi;
    float p = 1.5353362e-4f;
    p = fmaf(p, f, 1.3398874e-3f);
    p = fmaf(p, f, 9.6184374e-3f);
    p = fmaf(p, f, 5.5503325e-2f);
    p = fmaf(p, f, 2.4022648e-1f);
    p = fmaf(p, f, 6.9314720e-1f);
    p = fmaf(p, f, 1.0f);
    return __int_as_float(__float_as_int(p) + ((int)fi << 23));
}

#define LDSM4(r0, r1, r2, r3, addr)                                            \
    asm volatile("ldmatrix.sync.aligned.m8n8.x4.shared.b16 {%0,%1,%2,%3}, [%4];" \
                 : "=r"(r0), "=r"(r1), "=r"(r2), "=r"(r3) : "r"(addr))
#define LDSM4T(r0, r1, r2, r3, addr)                                           \
    asm volatile("ldmatrix.sync.aligned.m8n8.x4.trans.shared.b16 {%0,%1,%2,%3}, [%4];" \
                 : "=r"(r0), "=r"(r1), "=r"(r2), "=r"(r3) : "r"(addr))

#define CP16(dst, src) \
    asm volatile("cp.async.cg.shared.global [%0], [%1], 16;" :: "r"(dst), "l"(src))
#define CP_COMMIT() asm volatile("cp.async.commit_group;")
#define CP_WAIT(n) asm volatile("cp.async.wait_group %0;" :: "n"(n))

// ===================== pre-split: fp32 -> bf16 hi/lo =====================
__global__ __launch_bounds__(256) void conv_all(const float* __restrict__ emb,
                                                const float* __restrict__ Wq,
                                                const float* __restrict__ Wk,
                                                const float* __restrict__ Wv,
                                                const float* __restrict__ Wo) {
    const size_t NX = (size_t)MROWS * DDIM / 4;  // 2097152 float4
    size_t i = (size_t)blockIdx.x * 256 + threadIdx.x;
    float4 v;
    uint2 hi, lo;
    uint2 *dh, *dl;
    if (i < NX) {
        v = ((const float4*)emb)[i];
        dh = (uint2*)g_Xh + i;
        dl = (uint2*)g_Xl + i;
    } else {
        size_t j = i - NX;
        size_t w = j >> 18;  // 262144 float4 per weight matrix
        size_t rem = j & 262143;
        const float* W = (w == 0) ? Wq : (w == 1) ? Wk : (w == 2) ? Wv : Wo;
        v = ((const float4*)W)[rem];
        dh = (uint2*)g_Wh + j;
        dl = (uint2*)g_Wl + j;
    }
    split4(v, hi, lo);
    *dh = hi;
    *dl = lo;
}

// ===================== GEMM: Y = X @ W^T  (pure cp.async pipeline) =====================
// Inputs pre-split bf16: Xh/Xl [M,K], Wh/Wl [N,K]. CTA 128x128, 8 warps (2x4).
#define KC 32
#define NS (DDIM / KC)          // 32 stages
#define ROWB 80                 // bytes per smem row (32 bf16 + pad): conflict-free LDSM
#define GHALF 10240             // 128 rows * 80 B: one of Ah/Al/Bh/Bl
#define STAGE_B (4 * GHALF)     // 40960 B
#define NSTG 3
#define GEMM_SMEM (NSTG * STAGE_B)  // 122880 B

template <bool SPLIT_OUT>
__device__ __forceinline__ void mma_gemm(const __nv_bfloat16* __restrict__ Xh,
                                         const __nv_bfloat16* __restrict__ Xl,
                                         const __nv_bfloat16* __restrict__ Wh,
                                         const __nv_bfloat16* __restrict__ Wl,
                                         float* __restrict__ Yf,
                                         __nv_bfloat16* __restrict__ Yh,
                                         __nv_bfloat16* __restrict__ Yl) {
    extern __shared__ char smem_raw[];
    const uint32_t smb = smem_u32(smem_raw);

    const int tid = threadIdx.x;
    const int warp = tid >> 5, lane = tid & 31;
    const int wm = warp >> 2;      // 0..1 -> m offset wm*64
    const int wn = warp & 3;       // 0..3 -> n offset wn*32
    const int g = lane >> 2;
    const int tq = lane & 3;
    const int mi = lane >> 3;
    const int r8 = lane & 7;
    const int bm = blockIdx.y * 128;
    const int bn = blockIdx.x * 128;

    float acc[4][4][4];
#pragma unroll
    for (int i = 0; i < 4; i++)
#pragma unroll
        for (int j = 0; j < 4; j++)
#pragma unroll
            for (int r = 0; r < 4; r++) acc[i][j][r] = 0.f;

    // cp.async one K-stage into buffer `buf`: 4 arrays x 128 rows x 4 x 16B
    auto issue_stage = [&](int s, int buf) {
        const int k0 = s * KC;
        const uint32_t db = smb + buf * STAGE_B;
#pragma unroll
        for (int it = 0; it < 8; it++) {
            int idx = tid + it * 256;
            int arr = idx >> 9;
            int rem = idx & 511;
            int row = rem >> 2;
            int c16 = rem & 3;
            const __nv_bfloat16* src;
            if (arr == 0)      src = Xh + (size_t)(bm + row) * DDIM + k0 + c16 * 8;
            else if (arr == 1) src = Xl + (size_t)(bm + row) * DDIM + k0 + c16 * 8;
            else if (arr == 2) src = Wh + (size_t)(bn + row) * DDIM + k0 + c16 * 8;
            else               src = Wl + (size_t)(bn + row) * DDIM + k0 + c16 * 8;
            CP16(db + arr * GHALF + row * ROWB + c16 * 16, src);
        }
    };

    auto compute = [&](int buf) {
        const uint32_t Ah = smb + buf * STAGE_B;
        const uint32_t Bh = Ah + 2 * GHALF;
#pragma unroll
        for (int kt = 0; kt < 2; kt++) {
            uint32_t ah[4][4], al[4][4], bh[2][4], bl[2][4];
#pragma unroll
            for (int mt = 0; mt < 4; mt++) {
                uint32_t ar = Ah + (wm * 64 + mt * 16 + (mi & 1) * 8 + r8) * ROWB +
                              (kt * 16 + (mi >> 1) * 8) * 2;
                LDSM4(ah[mt][0], ah[mt][1], ah[mt][2], ah[mt][3], ar);
                LDSM4(al[mt][0], al[mt][1], al[mt][2], al[mt][3], ar + GHALF);
            }
#pragma unroll
            for (int j = 0; j < 2; j++) {
                uint32_t br = Bh + (wn * 32 + j * 16 + (mi >> 1) * 8 + r8) * ROWB +
                              (kt * 16 + (mi & 1) * 8) * 2;
                LDSM4(bh[j][0], bh[j][1], bh[j][2], bh[j][3], br);
                LDSM4(bl[j][0], bl[j][1], bl[j][2], bl[j][3], br + GHALF);
            }
#pragma unroll
            for (int mt = 0; mt < 4; mt++)
#pragma unroll
                for (int j = 0; j < 2; j++)
#pragma unroll
                    for (int h = 0; h < 2; h++)
                        mma16816(acc[mt][2 * j + h], ah[mt], bh[j] + 2 * h);
#pragma unroll
            for (int mt = 0; mt < 4; mt++)
#pragma unroll
                for (int j = 0; j < 2; j++)
#pragma unroll
                    for (int h = 0; h < 2; h++)
                        mma16816(acc[mt][2 * j + h], ah[mt], bl[j] + 2 * h);
#pragma unroll
            for (int mt = 0; mt < 4; mt++)
#pragma unroll
                for (int j = 0; j < 2; j++)
#pragma unroll
                    for (int h = 0; h < 2; h++)
                        mma16816(acc[mt][2 * j + h], al[mt], bh[j] + 2 * h);
        }
    };

    issue_stage(0, 0);
    CP_COMMIT();
    issue_stage(1, 1);
    CP_COMMIT();

    for (int s = 0; s < NS; s++) {
        if (s < NS - 1) { CP_WAIT(1); } else { CP_WAIT(0); }
        __syncthreads();
        if (s + 2 < NS) {
            issue_stage(s + 2, (s + 2) % NSTG);
            CP_COMMIT();
        }
        compute(s % NSTG);
    }

#pragma unroll
    for (int mt = 0; mt < 4; mt++) {
        const int row = bm + wm * 64 + mt * 16 + g;
#pragma unroll
        for (int nt = 0; nt < 4; nt++) {
            const int col = bn + wn * 32 + nt * 8 + tq * 2;
            if (SPLIT_OUT) {
                uint32_t* Yh32 = (uint32_t*)Yh;
                uint32_t* Yl32 = (uint32_t*)Yl;
                float a, b;
                uint32_t h0 = packbf(acc[mt][nt][0], acc[mt][nt][1]);
                unpackbf(h0, a, b);
                uint32_t l0 = packbf(acc[mt][nt][0] - a, acc[mt][nt][1] - b);
                Yh32[((size_t)row * DDIM + col) >> 1] = h0;
                Yl32[((size_t)row * DDIM + col) >> 1] = l0;
                uint32_t h1 = packbf(acc[mt][nt][2], acc[mt][nt][3]);
                unpackbf(h1, a, b);
                uint32_t l1 = packbf(acc[mt][nt][2] - a, acc[mt][nt][3] - b);
                Yh32[((size_t)(row + 8) * DDIM + col) >> 1] = h1;
                Yl32[((size_t)(row + 8) * DDIM + col) >> 1] = l1;
            } else {
                *(float2*)(Yf + (size_t)row * DDIM + col) =
                    make_float2(acc[mt][nt][0], acc[mt][nt][1]);
                *(float2*)(Yf + (size_t)(row + 8) * DDIM + col) =
                    make_float2(acc[mt][nt][2], acc[mt][nt][3]);
            }
        }
    }
}

__global__ __launch_bounds__(256, 1) void qkv_mma() {
    const int z = blockIdx.z;
    const __nv_bfloat16* Wh = g_Wh + (size_t)z * DDIM * DDIM;
    const __nv_bfloat16* Wl = g_Wl + (size_t)z * DDIM * DDIM;
    __nv_bfloat16* Yh = (z == 0) ? g_Qh : (z == 1) ? g_Kh : g_Vh;
    __nv_bfloat16* Yl = (z == 0) ? g_Ql : (z == 1) ? g_Kl : g_Vl;
    mma_gemm<true>(g_Xh, g_Xl, Wh, Wl, nullptr, Yh, Yl);
}

__global__ __launch_bounds__(256, 1) void oproj_mma(float* __restrict__ out) {
    mma_gemm<false>(g_Ah, g_Al, g_Wh + (size_t)3 * DDIM * DDIM,
                    g_Wl + (size_t)3 * DDIM * DDIM, out, nullptr, nullptr);
}

// ===================== Flash attention: 256 q-rows/CTA, 8 warps x 32 rows, 3-stage KV ======
#define NT (SLEN / 64)        // 32 kv tiles
#define RSTR 144              // smem row stride bytes
#define KVARR (64 * RSTR)     // 9216 B
#define KVBUF (4 * KVARR)     // 36864 B: Kh,Kl,Vh,Vl
#define QARR (256 * RSTR)     // 36864 B
#define ATT_SMEM (2 * QARR + 3 * KVBUF)  // 184320 B

__global__ __launch_bounds__(256, 1) void attn_mma() {
    extern __shared__ char smem_raw[];
    const uint32_t smb = smem_u32(smem_raw);
    const uint32_t q_u32 = smb;
    const uint32_t kv_u32 = smb + 2 * QARR;

    const int tid = threadIdx.x;
    const int wm = tid >> 5;
    const int lane = tid & 31;
    const int g = lane >> 2;
    const int tq = lane & 3;
    const int mi = lane >> 3;
    const int r8 = lane & 7;
    const int b = blockIdx.y >> 4;
    const int h = blockIdx.y & 15;
    const int q0 = blockIdx.x * 256;
    const size_t bS = (size_t)b * SLEN;
    const int hoff = h * DKH;

    // ---- Q loads (group 0) ----
#pragma unroll
    for (int p = 0; p < 2; p++) {
        int task = tid + p * 256;
        int arr = task >> 8, row = task & 255;
        const __nv_bfloat16* gp =
            (arr ? g_Ql : g_Qh) + (bS + q0 + row) * DDIM + hoff;
        uint32_t dst = q_u32 + arr * QARR + row * RSTR;
#pragma unroll
        for (int i = 0; i < 8; i++) CP16(dst + i * 16, gp + i * 8);
    }
    CP_COMMIT();

    auto load_kv = [&](int t, int bb) {
        int arr = tid >> 6, row = tid & 63;
        const __nv_bfloat16* gp =
            (arr == 0 ? g_Kh : arr == 1 ? g_Kl : arr == 2 ? g_Vh : g_Vl) +
            (bS + t * 64 + row) * DDIM + hoff;
        uint32_t dst = kv_u32 + bb * KVBUF + arr * KVARR + row * RSTR;
#pragma unroll
        for (int i = 0; i < 8; i++) CP16(dst + i * 16, gp + i * 8);
    };

    load_kv(0, 0);
    CP_COMMIT();
    load_kv(1, 1);
    CP_COMMIT();

    float s[2][8][4];
    float o[2][8][4];
    float ms[4] = {-1e30f, -1e30f, -1e30f, -1e30f};
    float l[4] = {0.f, 0.f, 0.f, 0.f};
#pragma unroll
    for (int mt = 0; mt < 2; mt++)
#pragma unroll
        for (int j = 0; j < 8; j++)
#pragma unroll
            for (int c = 0; c < 4; c++) o[mt][j][c] = 0.f;
    const float SCL = 0.125f * 1.4426950408889634f;

    for (int t = 0; t < NT; t++) {
        if (t < NT - 1) { CP_WAIT(1); } else { CP_WAIT(0); }
        __syncthreads();
        if (t + 2 < NT) {
            load_kv(t + 2, (t + 2) % 3);
            CP_COMMIT();
        }

        const uint32_t khb = kv_u32 + (t % 3) * KVBUF;
        const uint32_t vhb = khb + 2 * KVARR;

        // ---- S = Q K^T (3 term-major passes) ----
#pragma unroll
        for (int mt = 0; mt < 2; mt++)
#pragma unroll
            for (int j = 0; j < 8; j++)
#pragma unroll
                for (int c = 0; c < 4; c++) s[mt][j][c] = 0.f;
#pragma unroll
        for (int kt = 0; kt < 4; kt++) {
            uint32_t bh[4][4], bl[4][4];
#pragma unroll
            for (int j2 = 0; j2 < 4; j2++) {
                uint32_t addr = khb + (16 * j2 + (mi >> 1) * 8 + r8) * RSTR +
                                (kt * 16 + (mi & 1) * 8) * 2;
                LDSM4(bh[j2][0], bh[j2][1], bh[j2][2], bh[j2][3], addr);
                LDSM4(bl[j2][0], bl[j2][1], bl[j2][2], bl[j2][3], addr + KVARR);
            }
#pragma unroll
            for (int mt = 0; mt < 2; mt++) {
                uint32_t qaddr = q_u32 + (wm * 32 + mt * 16 + (mi & 1) * 8 + r8) * RSTR +
                                 (kt * 16 + (mi >> 1) * 8) * 2;
                uint32_t ah[4], al[4];
                LDSM4(ah[0], ah[1], ah[2], ah[3], qaddr);
                LDSM4(al[0], al[1], al[2], al[3], qaddr + QARR);
#pragma unroll
                for (int j2 = 0; j2 < 4; j2++) {
                    mma16816(s[mt][2 * j2], ah, bh[j2]);
                    mma16816(s[mt][2 * j2 + 1], ah, bh[j2] + 2);
                }
#pragma unroll
                for (int j2 = 0; j2 < 4; j2++) {
                    mma16816(s[mt][2 * j2], ah, bl[j2]);
                    mma16816(s[mt][2 * j2 + 1], ah, bl[j2] + 2);
                }
#pragma unroll
                for (int j2 = 0; j2 < 4; j2++) {
                    mma16816(s[mt][2 * j2], al, bh[j2]);
                    mma16816(s[mt][2 * j2 + 1], al, bh[j2] + 2);
                }
            }
        }

        // ---- online softmax ----
#pragma unroll
        for (int mt = 0; mt < 2; mt++) {
            float mx0 = -1e30f, mx1 = -1e30f;
#pragma unroll
            for (int j = 0; j < 8; j++) {
                mx0 = fmaxf(mx0, fmaxf(s[mt][j][0], s[mt][j][1]));
                mx1 = fmaxf(mx1, fmaxf(s[mt][j][2], s[mt][j][3]));
            }
            mx0 = fmaxf(mx0, __shfl_xor_sync(0xffffffffu, mx0, 1));
            mx0 = fmaxf(mx0, __shfl_xor_sync(0xffffffffu, mx0, 2));
            mx1 = fmaxf(mx1, __shfl_xor_sync(0xffffffffu, mx1, 1));
            mx1 = fmaxf(mx1, __shfl_xor_sync(0xffffffffu, mx1, 2));
            float ns0 = fmaxf(ms[2 * mt], mx0 * SCL);
            float ns1 = fmaxf(ms[2 * mt + 1], mx1 * SCL);
            float al0 = fexp2(ms[2 * mt] - ns0);
            float al1 = fexp2(ms[2 * mt + 1] - ns1);
            ms[2 * mt] = ns0;
            ms[2 * mt + 1] = ns1;
            float rs0 = 0.f, rs1 = 0.f;
#pragma unroll
            for (int j = 0; j < 8; j++) {
                float p0 = fexp2(fmaf(s[mt][j][0], SCL, -ns0));
                float p1 = fexp2(fmaf(s[mt][j][1], SCL, -ns0));
                float p2 = fexp2(fmaf(s[mt][j][2], SCL, -ns1));
                float p3 = fexp2(fmaf(s[mt][j][3], SCL, -ns1));
                s[mt][j][0] = p0; s[mt][j][1] = p1;
                s[mt][j][2] = p2; s[mt][j][3] = p3;
                rs0 += p0 + p1;
                rs1 += p2 + p3;
            }
            rs0 += __shfl_xor_sync(0xffffffffu, rs0, 1);
            rs0 += __shfl_xor_sync(0xffffffffu, rs0, 2);
            rs1 += __shfl_xor_sync(0xffffffffu, rs1, 1);
            rs1 += __shfl_xor_sync(0xffffffffu, rs1, 2);
            l[2 * mt] = l[2 * mt] * al0 + rs0;
            l[2 * mt + 1] = l[2 * mt + 1] * al1 + rs1;
#pragma unroll
            for (int j = 0; j < 8; j++) {
                o[mt][j][0] *= al0; o[mt][j][1] *= al0;
                o[mt][j][2] *= al1; o[mt][j][3] *= al1;
            }
        }

        // ---- O += P V ----
#pragma unroll
        for (int kt = 0; kt < 4; kt++) {
            uint32_t vh[4][4], vl[4][4];
#pragma unroll
            for (int j2 = 0; j2 < 4; j2++) {
                uint32_t addr = vhb + (kt * 16 + (mi & 1) * 8 + r8) * RSTR +
                                (16 * j2 + (mi >> 1) * 8) * 2;
                LDSM4T(vh[j2][0], vh[j2][1], vh[j2][2], vh[j2][3], addr);
                LDSM4T(vl[j2][0], vl[j2][1], vl[j2][2], vl[j2][3], addr + KVARR);
            }
#pragma unroll
            for (int mt = 0; mt < 2; mt++) {
                uint32_t aph[4], apl[4];
#pragma unroll
                for (int u = 0; u < 2; u++) {
                    const int j = 2 * kt + u;
                    uint32_t h0 = packbf(s[mt][j][0], s[mt][j][1]);
                    uint32_t h1 = packbf(s[mt][j][2], s[mt][j][3]);
                    float a, bb, c, d;
                    unpackbf(h0, a, bb);
                    unpackbf(h1, c, d);
                    aph[2 * u] = h0;
                    aph[2 * u + 1] = h1;
                    apl[2 * u] = packbf(s[mt][j][0] - a, s[mt][j][1] - bb);
                    apl[2 * u + 1] = packbf(s[mt][j][2] - c, s[mt][j][3] - d);
                }
#pragma unroll
                for (int j2 = 0; j2 < 4; j2++) {
                    mma16816(o[mt][2 * j2], aph, vh[j2]);
                    mma16816(o[mt][2 * j2 + 1], aph, vh[j2] + 2);
                }
#pragma unroll
                for (int j2 = 0; j2 < 4; j2++) {
                    mma16816(o[mt][2 * j2], aph, vl[j2]);
                    mma16816(o[mt][2 * j2 + 1], aph, vl[j2] + 2);
                }
#pragma unroll
                for (int j2 = 0; j2 < 4; j2++) {
                    mma16816(o[mt][2 * j2], apl, vh[j2]);
                    mma16816(o[mt][2 * j2 + 1], apl, vh[j2] + 2);
                }
            }
        }
    }

    // ---- epilogue: normalize, emit bf16 hi/lo for oproj ----
    uint32_t* Ah32 = (uint32_t*)g_Ah;
    uint32_t* Al32 = (uint32_t*)g_Al;
#pragma unroll
    for (int mt = 0; mt < 2; mt++) {
        const float inv0 = 1.f / l[2 * mt];
        const float inv1 = 1.f / l[2 * mt + 1];
        const int row0 = q0 + wm * 32 + mt * 16 + g;
#pragma unroll
        for (int j = 0; j < 8; j++) {
            const int col = hoff + j * 8 + tq * 2;
            float v0 = o[mt][j][0] * inv0, v1 = o[mt][j][1] * inv0;
            float v2 = o[mt][j][2] * inv1, v3 = o[mt][j][3] * inv1;
            float a, b;
            uint32_t h0 = packbf(v0, v1);
            unpackbf(h0, a, b);
            uint32_t l0 = packbf(v0 - a, v1 - b);
            Ah32[((bS + row0) * DDIM + col) >> 1] = h0;
            Al32[((bS + row0) * DDIM + col) >> 1] = l0;
            uint32_t h1 = packbf(v2, v3);
            unpackbf(h1, a, b);
            uint32_t l1 = packbf(v2 - a, v3 - b);
            Ah32[((bS + row0 + 8) * DDIM + col) >> 1] = h1;
            Al32[((bS + row0 + 8) * DDIM + col) >> 1] = l1;
        }
    }
}

// ======================= launch =======================
extern "C" void kernel_launch(void* const* d_in, const int* in_sizes, int n_in,
                              void* d_out, int out_size) {
    const float* emb = (const float*)d_in[0];
    const float* Wq  = (const float*)d_in[1];
    const float* Wk  = (const float*)d_in[2];
    const float* Wv  = (const float*)d_in[3];
    const float* Wo  = (const float*)d_in[4];
    float* out = (float*)d_out;

    cudaFuncSetAttribute(qkv_mma, cudaFuncAttributeMaxDynamicSharedMemorySize, GEMM_SMEM);
    cudaFuncSetAttribute(oproj_mma, cudaFuncAttributeMaxDynamicSharedMemorySize, GEMM_SMEM);
    cudaFuncSetAttribute(attn_mma, cudaFuncAttributeMaxDynamicSharedMemorySize, ATT_SMEM);

    // pre-split fp32 -> bf16 hi/lo
    const int NCONV = (MROWS * DDIM / 4 + 4 * DDIM * DDIM / 4) / 256;  // 12288
    conv_all<<<NCONV, 256>>>(emb, Wq, Wk, Wv, Wo);

    dim3 ggrid(DDIM / 128, MROWS / 128, 3);
    qkv_mma<<<ggrid, 256, GEMM_SMEM>>>();

    dim3 agrid(SLEN / 256, BATCH * NHEAD);
    attn_mma<<<agrid, 256, ATT_SMEM>>>();

    dim3 ogrid(DDIM / 128, MROWS / 128, 1);
    oproj_mma<<<ogrid, 256, GEMM_SMEM>>>(out);
}